// round 9
// baseline (speedup 1.0000x reference)
#include <cuda_runtime.h>
#include <math.h>

#define NN 100000
#define NG 64
#define D  128
#define EMAX 2600000   // E + 8*NN padding headroom

typedef unsigned long long ull;

// -------- scratch (device globals; no runtime allocation) --------
__device__ float g_h   [(size_t)(NN + 8) * D]; // dinv-scaled GEMM output; row NN stays zero (pad target)
__device__ float g_agg [(size_t)NN * D];       // layer-2 aggregated output (pool input)
__device__ float g_elu [(size_t)NN * D];       // elu(layer-1 agg) = layer-2 GEMM input
__device__ float g_dinv[NN];                   // deg^{-1/2}
__device__ int   g_cnti[NN];                   // per-dst edge counts (re-zeroed by k_scan)
__device__ int   g_off [NN + 1];               // CSR offsets (8-aligned regions)
__device__ int   g_cur [NN];                   // fill cursors
__device__ __align__(16) int g_srcs[EMAX];     // CSR adjacency, pad entries = NN
__device__ float g_pool[NG * D];
__device__ float g_cnt [NG];

// ---------------- CSR build ----------------
__global__ void k_count(const int* __restrict__ ei, int E) {
    int e = blockIdx.x * blockDim.x + threadIdx.x;
    if (e >= E) return;
    unsigned dst = (unsigned)ei[(size_t)E + e];
    if (dst < NN) atomicAdd(&g_cnti[dst], 1);
}

#define SCAN_T 1024
// single block: exclusive scan of 8-aligned region sizes -> off/cur, dinv,
// pad g_srcs, re-zero g_cnti, zero pool accumulators.
__global__ void k_scan() {
    __shared__ int ssum[SCAN_T];
    int t = threadIdx.x;

    // zero pool accumulators (fused here to save launches)
    for (int i = t; i < NG * D; i += SCAN_T) g_pool[i] = 0.f;
    if (t < NG) g_cnt[t] = 0.f;

    int per = (NN + SCAN_T - 1) / SCAN_T;
    int lo = t * per, hi = lo + per; if (hi > NN) hi = NN;
    int s = 0;
    for (int i = lo; i < hi; i++) s += (g_cnti[i] + 7) & ~7;
    ssum[t] = s;
    __syncthreads();
    for (int ofs = 1; ofs < SCAN_T; ofs <<= 1) {
        int v = (t >= ofs) ? ssum[t - ofs] : 0;
        __syncthreads();
        ssum[t] += v;
        __syncthreads();
    }
    int run = (t == 0) ? 0 : ssum[t - 1];
    for (int i = lo; i < hi; i++) {
        int c  = g_cnti[i];
        int ca = (c + 7) & ~7;
        g_off[i] = run;
        g_cur[i] = run;
        g_dinv[i] = rsqrtf((float)c + 1.0f);   // +1 self loop
        for (int p = run + c; p < run + ca && p < EMAX; p++) g_srcs[p] = NN;
        g_cnti[i] = 0;                          // ready for next replay
        run += ca;
    }
    if (t == SCAN_T - 1) g_off[NN] = run;
}

__global__ void k_fill(const int* __restrict__ ei, int E) {
    int e = blockIdx.x * blockDim.x + threadIdx.x;
    if (e >= E) return;
    unsigned src = (unsigned)ei[e];
    unsigned dst = (unsigned)ei[(size_t)E + e];
    if (src >= NN || dst >= NN) return;
    int pos = atomicAdd(&g_cur[dst], 1);
    if (pos < EMAX) g_srcs[pos] = (int)src;
}

// ---------------- SGEMM (f32x2) : g_h = dinv * (X @ W) --------------------
#define BM 128
#define BN 128
#define BKK 32
#define KTILES (D / BKK)   // 4

#define FMA2(d, a, b) asm("fma.rn.f32x2 %0, %1, %2, %3;" : "=l"(d) : "l"(a), "l"(b), "l"(d))

__device__ __forceinline__
void gemm_body(const float* __restrict__ X, const float* __restrict__ W) {
    __shared__ float sA [BKK][BM];       // 16 KB, [k][m]
    __shared__ float sBd[BKK][2 * BN];   // 32 KB, duplicated cols

    int tid = threadIdx.x;
    int tm  = tid >> 4;
    int tn  = tid & 15;
    int m0  = blockIdx.x * BM;

    int arow = tid >> 1;
    int ak0  = (tid & 1) * 16;

    ull acc[4][8];
#pragma unroll
    for (int i = 0; i < 4; i++)
#pragma unroll
        for (int j = 0; j < 8; j++) acc[i][j] = 0ull;

    float4 ra[4];
    {
        int row = m0 + arow;
        const float4* xr = (const float4*)(X + (size_t)row * D) + (ak0 >> 2);
#pragma unroll
        for (int i = 0; i < 4; i++)
            ra[i] = (row < NN) ? __ldg(&xr[i]) : make_float4(0.f, 0.f, 0.f, 0.f);
    }

    for (int t = 0; t < KTILES; t++) {
#pragma unroll
        for (int i = 0; i < 4; i++) {
            sA[ak0 + i * 4 + 0][arow] = ra[i].x;
            sA[ak0 + i * 4 + 1][arow] = ra[i].y;
            sA[ak0 + i * 4 + 2][arow] = ra[i].z;
            sA[ak0 + i * 4 + 3][arow] = ra[i].w;
        }
        {
            const float4* wg = (const float4*)(W + (size_t)t * BKK * D);
#pragma unroll
            for (int i = 0; i < 4; i++) {
                float4 v = __ldg(&wg[tid + 256 * i]);
                int p = tid + 256 * i;
                int k = p >> 5;
                int c = (p & 31) * 4;
                *(float4*)&sBd[k][2 * c]     = make_float4(v.x, v.x, v.y, v.y);
                *(float4*)&sBd[k][2 * c + 4] = make_float4(v.z, v.z, v.w, v.w);
            }
        }
        __syncthreads();

        if (t + 1 < KTILES) {
            int kt = (t + 1) * BKK;
            int row = m0 + arow;
            const float4* xr = (const float4*)(X + (size_t)row * D + kt) + (ak0 >> 2);
#pragma unroll
            for (int i = 0; i < 4; i++)
                ra[i] = (row < NN) ? __ldg(&xr[i]) : make_float4(0.f, 0.f, 0.f, 0.f);
        }

#pragma unroll
        for (int k = 0; k < BKK; k++) {
            ulonglong2 alo = *(ulonglong2*)&sA[k][tm * 4];
            ulonglong2 ahi = *(ulonglong2*)&sA[k][64 + tm * 4];
            ull ap[4] = {alo.x, alo.y, ahi.x, ahi.y};
            ull bp[8];
#pragma unroll
            for (int jj = 0; jj < 8; jj++)
                bp[jj] = *(ull*)&sBd[k][2 * (tn + 16 * jj)];
#pragma unroll
            for (int r = 0; r < 4; r++)
#pragma unroll
                for (int jj = 0; jj < 8; jj++)
                    FMA2(acc[r][jj], ap[r], bp[jj]);
        }
        __syncthreads();
    }

    // epilogue: scale by dinv[row], store
#pragma unroll
    for (int r = 0; r < 4; r++) {
        int row0 = m0 + (r >> 1) * 64 + tm * 4 + (r & 1) * 2;
        int row1 = row0 + 1;
        bool ok0 = row0 < NN, ok1 = row1 < NN;
        float d0 = ok0 ? g_dinv[row0] : 0.f;
        float d1 = ok1 ? g_dinv[row1] : 0.f;
        float* h0 = g_h + (size_t)row0 * D;
        float* h1 = g_h + (size_t)row1 * D;
#pragma unroll
        for (int jj = 0; jj < 8; jj++) {
            ull v = acc[r][jj];
            int col = tn + 16 * jj;
            if (ok0) h0[col] = d0 * __uint_as_float((unsigned)v);
            if (ok1) h1[col] = d1 * __uint_as_float((unsigned)(v >> 32));
        }
    }
}

__global__ __launch_bounds__(256, 2)
void k_gemm_l1(const float* __restrict__ X, const float* __restrict__ W) {
    gemm_body(X, W);
}

__global__ __launch_bounds__(256, 2)
void k_gemm_l2(const float* __restrict__ W) {
    gemm_body(g_elu, W);
}

// ---------------- CSR gather (warp/node, padded regions of 8) ------------
// g_h holds hs = dinv*h.  out = bias + dinv[n] * ( hs[n] + sum_s hs[s] )
template<bool DO_ELU>
__global__ void k_gather(const float* __restrict__ bias) {
    int node = (blockIdx.x * blockDim.x + threadIdx.x) >> 5;
    int lane = threadIdx.x & 31;
    if (node >= NN) return;

    float dv = g_dinv[node];
    float4 acc = __ldg((const float4*)(g_h + (size_t)node * D) + lane); // self = hs[n]

    int j   = g_off[node];
    int end = g_off[node + 1];
    if (end > EMAX) end = EMAX;

    for (; j < end; j += 8) {
        int4 sa = __ldg((const int4*)(g_srcs + j));
        int4 sb = __ldg((const int4*)(g_srcs + j + 4));
        float4 v0 = __ldg((const float4*)(g_h + (size_t)sa.x * D) + lane);
        float4 v1 = __ldg((const float4*)(g_h + (size_t)sa.y * D) + lane);
        float4 v2 = __ldg((const float4*)(g_h + (size_t)sa.z * D) + lane);
        float4 v3 = __ldg((const float4*)(g_h + (size_t)sa.w * D) + lane);
        float4 v4 = __ldg((const float4*)(g_h + (size_t)sb.x * D) + lane);
        float4 v5 = __ldg((const float4*)(g_h + (size_t)sb.y * D) + lane);
        float4 v6 = __ldg((const float4*)(g_h + (size_t)sb.z * D) + lane);
        float4 v7 = __ldg((const float4*)(g_h + (size_t)sb.w * D) + lane);
        acc.x += ((v0.x + v1.x) + (v2.x + v3.x)) + ((v4.x + v5.x) + (v6.x + v7.x));
        acc.y += ((v0.y + v1.y) + (v2.y + v3.y)) + ((v4.y + v5.y) + (v6.y + v7.y));
        acc.z += ((v0.z + v1.z) + (v2.z + v3.z)) + ((v4.z + v5.z) + (v6.z + v7.z));
        acc.w += ((v0.w + v1.w) + (v2.w + v3.w)) + ((v4.w + v5.w) + (v6.w + v7.w));
    }

    float4 b = __ldg((const float4*)bias + lane);
    acc.x = b.x + dv * acc.x;
    acc.y = b.y + dv * acc.y;
    acc.z = b.z + dv * acc.z;
    acc.w = b.w + dv * acc.w;

    if (DO_ELU) {
        acc.x = acc.x > 0.f ? acc.x : expm1f(acc.x);
        acc.y = acc.y > 0.f ? acc.y : expm1f(acc.y);
        acc.z = acc.z > 0.f ? acc.z : expm1f(acc.z);
        acc.w = acc.w > 0.f ? acc.w : expm1f(acc.w);
        ((float4*)(g_elu + (size_t)node * D))[lane] = acc;
    } else {
        ((float4*)(g_agg + (size_t)node * D))[lane] = acc;
    }
}

// ---------------- pooling ----------------
#define NPB 256
__global__ void k_pool(const int* __restrict__ batch) {
    int f = threadIdx.x;
    int start = blockIdx.x * NPB;
    if (start >= NN) return;
    int end = start + NPB; if (end > NN) end = NN;

    float acc = 0.f;
    int cur = batch[start];
    if ((unsigned)cur >= NG) cur = 0;
    for (int n = start; n < end; n++) {
        int b = batch[n];
        if ((unsigned)b >= NG) b = 0;
        if (b != cur) {
            atomicAdd(&g_pool[cur * D + f], acc);
            acc = 0.f; cur = b;
        }
        acc += g_agg[(size_t)n * D + f];
    }
    atomicAdd(&g_pool[cur * D + f], acc);

    if (f == 0) {
        float c = 0.f;
        int cur2 = batch[start];
        if ((unsigned)cur2 >= NG) cur2 = 0;
        for (int n = start; n < end; n++) {
            int b = batch[n];
            if ((unsigned)b >= NG) b = 0;
            if (b != cur2) { atomicAdd(&g_cnt[cur2], c); c = 0.f; cur2 = b; }
            c += 1.0f;
        }
        atomicAdd(&g_cnt[cur2], c);
    }
}

// ---------------- final MLP + log_softmax ----------------
__global__ void k_mlp(const float* __restrict__ fc1W, const float* __restrict__ fc1b,
                      const float* __restrict__ fc2W, const float* __restrict__ fc2b,
                      float* __restrict__ out) {
    int g = blockIdx.x;
    int lane = threadIdx.x;
    __shared__ float mean[D];
    __shared__ float m1[20];
    __shared__ float z[10];
    __shared__ float lse;

    float cnt = fmaxf(g_cnt[g], 1.0f);
    for (int k = lane; k < D; k += 32) mean[k] = g_pool[g * D + k] / cnt;
    __syncwarp();

    if (lane < 20) {
        float s = fc1b[lane];
        for (int k = 0; k < D; k++) s = fmaf(mean[k], fc1W[k * 20 + lane], s);
        m1[lane] = fmaxf(s, 0.0f);
    }
    __syncwarp();

    if (lane < 10) {
        float s = fc2b[lane];
        for (int k = 0; k < 20; k++) s = fmaf(m1[k], fc2W[k * 10 + lane], s);
        z[lane] = s;
    }
    __syncwarp();

    if (lane == 0) {
        float mx = z[0];
        for (int j = 1; j < 10; j++) mx = fmaxf(mx, z[j]);
        float s = 0.f;
        for (int j = 0; j < 10; j++) s += expf(z[j] - mx);
        lse = mx + logf(s);
    }
    __syncwarp();

    if (lane < 10) out[g * 10 + lane] = z[lane] - lse;
}

// ---------------- launch ----------------
extern "C" void kernel_launch(void* const* d_in, const int* in_sizes, int n_in,
                              void* d_out, int out_size) {
    int ix = -1, iei = -1, ib = -1, iW[2] = {-1, -1}, ibias[2] = {-1, -1};
    int if1W = -1, if1b = -1, if2W = -1, if2b = -1;
    int nW = 0, nbias = 0;
    for (int i = 0; i < n_in; i++) {
        int s = in_sizes[i];
        if      (s == NN * D)            ix = i;
        else if (s == NN)                ib = i;
        else if (s == D * D && nW < 2)   iW[nW++] = i;
        else if (s == D && nbias < 2)    ibias[nbias++] = i;
        else if (s == D * 20)            if1W = i;
        else if (s == 20)                if1b = i;
        else if (s == 20 * 10)           if2W = i;
        else if (s == 10)                if2b = i;
        else if (s > NN)                 iei = i;
    }
    bool ok = (ix >= 0 && iei >= 0 && ib >= 0 && nW == 2 && nbias == 2 &&
               if1W >= 0 && if1b >= 0 && if2W >= 0 && if2b >= 0);
    if (!ok) {
        ix = 0; iei = 1; ib = 2; iW[0] = 3; ibias[0] = 4; iW[1] = 5; ibias[1] = 6;
        if1W = 7; if1b = 8; if2W = 9; if2b = 10;
    }

    const float* x     = (const float*)d_in[ix];
    const int*   ei    = (const int*)d_in[iei];
    const int*   batch = (const int*)d_in[ib];
    const float* W1   = (const float*)d_in[iW[0]];
    const float* b1   = (const float*)d_in[ibias[0]];
    const float* W2   = (const float*)d_in[iW[1]];
    const float* b2   = (const float*)d_in[ibias[1]];
    const float* fc1W = (const float*)d_in[if1W];
    const float* fc1b = (const float*)d_in[if1b];
    const float* fc2W = (const float*)d_in[if2W];
    const float* fc2b = (const float*)d_in[if2b];
    float* out = (float*)d_out;

    int E = in_sizes[iei] / 2;

    const int T = 256;
    int nb_edges  = (E + T - 1) / T;
    int nb_gemm   = (NN + BM - 1) / BM;
    int nb_gather = (int)(((size_t)NN * 32 + T - 1) / T);
    int nb_pool   = (NN + NPB - 1) / NPB;

    k_count<<<nb_edges, T>>>(ei, E);                  // 0
    k_scan<<<1, SCAN_T>>>();                          // 1 (scan+dinv+pads+zeroing)
    k_fill<<<nb_edges, T>>>(ei, E);                   // 2
    k_gemm_l1<<<nb_gemm, 256>>>(x, W1);               // 3  <- profiled
    k_gather<true><<<nb_gather, T>>>(b1);             // 4  -> g_elu
    k_gemm_l2<<<nb_gemm, 256>>>(W2);                  // 5
    k_gather<false><<<nb_gather, T>>>(b2);            // 6  -> g_agg
    k_pool<<<nb_pool, D>>>(batch);                    // 7
    k_mlp<<<NG, 32>>>(fc1W, fc1b, fc2W, fc2b, out);   // 8
}